// round 11
// baseline (speedup 1.0000x reference)
#include <cuda_runtime.h>
#include <math.h>
#include <stdint.h>

// ---------------- problem constants ----------------
#define NN 50000         // nodes
#define NE 600000        // edges
#define HD 128           // hidden
#define NG 64            // graphs
#define K3 384           // 3*H
#define NLAYERS 2
#define NSTEPS 2
#define NSTAGE 3

// ---------------- device scratch (no allocs; zero-initialized at load) ----------------
__device__ float d_h[(size_t)NN * HD];
__device__ float d_S[(size_t)NN * K3];
__device__ float d_a[(size_t)NN * HD];
__device__ float d_gi[(size_t)NN * K3];   // planes: r | z | i_n
__device__ float d_gh[(size_t)NN * K3];   // planes: h_n | h32 (rounded h copy)
__device__ float d_deg[(size_t)NN * 3];
__device__ int   d_cnt[NN];               // zeroed by scan kernel after use (replay-safe)
__device__ int   d_rowptr[NN + 1];
__device__ int   d_cursor[NN];
__device__ int   d_edges[NE];
__device__ int   d_goff[NG + 1];
__device__ float d_wcatT[2 * HD * K3];    // per layer: [128 out][384 k], tf32-rounded
__device__ float d_wih32[2 * K3 * HD];    // tf32-rounded W_ih
__device__ float d_whh32[2 * K3 * HD];    // tf32-rounded W_hh
__device__ float d_agg[NG * K3];

__device__ __forceinline__ unsigned cvt_tf32(float x) {
    unsigned r;
    asm("cvt.rna.tf32.f32 %0, %1;" : "=r"(r) : "f"(x));
    return r;
}
__device__ __forceinline__ float rnd_tf32(float x) {
    return __uint_as_float(cvt_tf32(x));
}
__device__ __forceinline__ void f4add(float4& a, const float4& b) {
    a.x += b.x; a.y += b.y; a.z += b.z; a.w += b.w;
}
__device__ __forceinline__ void cp_async16(unsigned saddr, const void* gptr, int szbytes) {
    asm volatile("cp.async.cg.shared.global [%0], [%1], 16, %2;"
                 :: "r"(saddr), "l"(gptr), "r"(szbytes));
}
#define CP_COMMIT() asm volatile("cp.async.commit_group;")
#define CP_WAIT(n)  asm volatile("cp.async.wait_group %0;" :: "n"(n))

// ---------------- setup kernels ----------------

__global__ void count_edges_kernel(const int* __restrict__ dst, int* __restrict__ cnt) {
    int e = blockIdx.x * blockDim.x + threadIdx.x;
    if (e < NE) atomicAdd(&cnt[dst[e]], 1);
}

// coalesced scan: stage counts in smem, chunk-scan, zero cnt for next replay; fuse goff.
#define SCAN_SMEM (NN * 4)
__global__ void scan_goff_kernel(int* __restrict__ cnt, int* __restrict__ rowptr,
                                 int* __restrict__ cursor,
                                 const int* __restrict__ graph_id, int* __restrict__ goff) {
    extern __shared__ int sc[];
    const int CH = (NN + 1023) / 1024;   // 49
    int tid = threadIdx.x;

    // coalesced stage-in + zero for next replay
    for (int q = 0; q < CH; ++q) {
        int i = q * 1024 + tid;
        if (i < NN) { sc[i] = cnt[i]; cnt[i] = 0; }
    }
    __syncthreads();

    int s = tid * CH;
    int e = s + CH < NN ? s + CH : NN;
    int sum = 0;
    for (int i = s; i < e; ++i) sum += sc[i];

    __shared__ int warpsums[32];
    int lane = tid & 31, wid = tid >> 5;
    int v = sum;
#pragma unroll
    for (int off = 1; off < 32; off <<= 1) {
        int t = __shfl_up_sync(0xFFFFFFFFu, v, off);
        if (lane >= off) v += t;
    }
    if (lane == 31) warpsums[wid] = v;
    __syncthreads();
    if (wid == 0) {
        int w = warpsums[lane];
#pragma unroll
        for (int off = 1; off < 32; off <<= 1) {
            int t = __shfl_up_sync(0xFFFFFFFFu, w, off);
            if (lane >= off) w += t;
        }
        warpsums[lane] = w;
    }
    __syncthreads();
    int run = (v - sum) + (wid > 0 ? warpsums[wid - 1] : 0);
    for (int i = s; i < e; ++i) {
        int c = sc[i];
        cursor[i] = run;
        run += c;
        rowptr[i + 1] = run;
    }
    if (tid == 0) rowptr[0] = 0;

    // goff: graph_id sorted -> lower_bound
    if (tid <= NG) {
        if (tid == NG) goff[NG] = NN;
        else {
            int lo = 0, hi = NN;
            while (lo < hi) {
                int mid = (lo + hi) >> 1;
                if (graph_id[mid] < tid) lo = mid + 1; else hi = mid;
            }
            goff[tid] = lo;
        }
    }
}

__global__ void place_edges_kernel(const int* __restrict__ src, const int* __restrict__ dst,
                                   const int* __restrict__ etype, int* __restrict__ cursor,
                                   int* __restrict__ edges) {
    int e = blockIdx.x * blockDim.x + threadIdx.x;
    if (e >= NE) return;
    int d = dst[e];
    int pos = atomicAdd(&cursor[d], 1);
    edges[pos] = src[e] | (etype[e] << 24);
}

// embed (h + rounded h32) + Wl transpose/round + W_ih/W_hh round — all pure copies
__global__ void embed_weights_kernel(const int* __restrict__ text_idx,
                                     const float* __restrict__ emb,
                                     float* __restrict__ h, float* __restrict__ h32,
                                     const float* __restrict__ Wl, float* __restrict__ wcatT,
                                     const float* __restrict__ Wih, const float* __restrict__ Whh,
                                     float* __restrict__ wih32, float* __restrict__ whh32) {
    int idx = blockIdx.x * blockDim.x + threadIdx.x;
    if (idx < 2 * 3 * 128 * 128) {
        int o  = idx & 127;
        int hh = (idx >> 7) & 127;
        int lt = idx >> 14;
        int t  = lt % 3;
        int l  = lt / 3;
        wcatT[(size_t)l * HD * K3 + (size_t)o * K3 + t * 128 + hh] = rnd_tf32(Wl[idx]);
    }
    if (idx < 2 * K3 * HD) {
        wih32[idx] = rnd_tf32(Wih[idx]);
        whh32[idx] = rnd_tf32(Whh[idx]);
    }
    if (idx < NN * HD) {
        int n = idx >> 7, c = idx & 127;
        float v = emb[(size_t)text_idx[n] * HD + c];
        h[idx] = v;
        h32[idx] = rnd_tf32(v);
    }
}

// segment mean of current h -> agg slot
__global__ void mean_kernel(const float* __restrict__ h, const int* __restrict__ goff,
                            float* __restrict__ agg, int slot) {
    int g = blockIdx.x;
    int c = threadIdx.x; // 128
    int s = goff[g], e = goff[g + 1];
    float a0 = 0.f, a1 = 0.f, a2 = 0.f, a3 = 0.f;
    int r = s;
    for (; r + 4 <= e; r += 4) {
        a0 += h[(size_t)(r + 0) * HD + c];
        a1 += h[(size_t)(r + 1) * HD + c];
        a2 += h[(size_t)(r + 2) * HD + c];
        a3 += h[(size_t)(r + 3) * HD + c];
    }
    for (; r < e; ++r) a0 += h[(size_t)r * HD + c];
    float acc = (a0 + a1) + (a2 + a3);
    float cntf = (float)((e - s) > 0 ? (e - s) : 1);
    agg[g * K3 + slot * HD + c] = acc / cntf;
}

// slot-0 mean recomputed from emb[text_idx] (order-free)
__global__ void mean0_emb_kernel(const int* __restrict__ text_idx,
                                 const float* __restrict__ emb,
                                 const int* __restrict__ goff,
                                 float* __restrict__ agg) {
    int g = blockIdx.x;
    int c = threadIdx.x; // 128
    int s = goff[g], e = goff[g + 1];
    float a0 = 0.f, a1 = 0.f, a2 = 0.f, a3 = 0.f;
    int r = s;
    for (; r + 4 <= e; r += 4) {
        a0 += emb[(size_t)text_idx[r + 0] * HD + c];
        a1 += emb[(size_t)text_idx[r + 1] * HD + c];
        a2 += emb[(size_t)text_idx[r + 2] * HD + c];
        a3 += emb[(size_t)text_idx[r + 3] * HD + c];
    }
    for (; r < e; ++r) a0 += emb[(size_t)text_idx[r] * HD + c];
    float acc = (a0 + a1) + (a2 + a3);
    float cntf = (float)((e - s) > 0 ? (e - s) : 1);
    agg[g * K3 + c] = acc / cntf;
}

// one warp per dst node: per-etype sums -> S pre-rounded to tf32
__global__ void aggregate_kernel(const float* __restrict__ h, const int* __restrict__ rowptr,
                                 const int* __restrict__ edges, float* __restrict__ S,
                                 float* __restrict__ deg) {
    int warp = (blockIdx.x * blockDim.x + threadIdx.x) >> 5;
    int lane = threadIdx.x & 31;
    if (warp >= NN) return;
    int s = rowptr[warp], e = rowptr[warp + 1];
    float4 a0 = {0,0,0,0}, a1 = {0,0,0,0}, a2 = {0,0,0,0};
    int c0 = 0, c1 = 0, c2 = 0;
    const float4* h4 = (const float4*)h;
    for (int i = s; i < e; ++i) {
        int p = edges[i];
        int srcn = p & 0xFFFFFF;
        int t = p >> 24;
        float4 v = h4[(size_t)srcn * 32 + lane];
        if (t == 0)      { f4add(a0, v); c0++; }
        else if (t == 1) { f4add(a1, v); c1++; }
        else             { f4add(a2, v); c2++; }
    }
    uint4* S4 = (uint4*)S;
    size_t base = (size_t)warp * 96;
    S4[base + lane]      = make_uint4(cvt_tf32(a0.x), cvt_tf32(a0.y), cvt_tf32(a0.z), cvt_tf32(a0.w));
    S4[base + 32 + lane] = make_uint4(cvt_tf32(a1.x), cvt_tf32(a1.y), cvt_tf32(a1.z), cvt_tf32(a1.w));
    S4[base + 64 + lane] = make_uint4(cvt_tf32(a2.x), cvt_tf32(a2.y), cvt_tf32(a2.z), cvt_tf32(a2.w));
    if (lane == 0) {
        deg[(size_t)warp * 3 + 0] = (float)c0;
        deg[(size_t)warp * 3 + 1] = (float)c1;
        deg[(size_t)warp * 3 + 2] = (float)c2;
    }
}

// ---------------- TF32 GEMM, cp.async 3-stage pipeline ----------------
#define TILE_U32   (128 * 36)
#define GEMM_SMEM_BYTES (NSTAGE * TILE_U32 * 2 * 4)

// C[m][j] = sum_k A[m][k]*B[j][k]; +deg-weighted bl3 epilogue; output rounded to tf32
__global__ __launch_bounds__(256, 2) void tf32gemm_abt_kernel(
    const float* __restrict__ A, const float* __restrict__ B, float* __restrict__ C,
    int M, int K, int J,
    const float* __restrict__ deg, const float* __restrict__ bl3)
{
    extern __shared__ unsigned sm[];
    unsigned* As = sm;
    unsigned* Bs = sm + NSTAGE * TILE_U32;

    const int tid = threadIdx.x;
    const int warp = tid >> 5;
    const int lane = tid & 31;
    const int g    = lane >> 2;
    const int tg   = lane & 3;
    const int wm   = (warp >> 2) * 64;
    const int wn   = (warp & 3) * 32;
    const int m0   = blockIdx.x * 128;

    float acc[4][4][4];
#pragma unroll
    for (int mi = 0; mi < 4; ++mi)
#pragma unroll
        for (int ni = 0; ni < 4; ++ni)
#pragma unroll
            for (int q = 0; q < 4; ++q) acc[mi][ni][q] = 0.f;

    const int numT = K >> 5;

    auto GLOAD = [&](int stg, int t) {
        int k0 = t << 5;
        unsigned abase = (unsigned)__cvta_generic_to_shared(As + (size_t)stg * TILE_U32);
        unsigned bbase = (unsigned)__cvta_generic_to_shared(Bs + (size_t)stg * TILE_U32);
#pragma unroll
        for (int u = 0; u < 4; ++u) {
            int f  = tid + u * 256;
            int r  = f >> 3;
            int kq = (f & 7) << 2;
            int gm = m0 + r;
            int gmc = gm < M ? gm : (M - 1);
            cp_async16(abase + (unsigned)(r * 36 + kq) * 4,
                       A + (size_t)gmc * K + k0 + kq, gm < M ? 16 : 0);
            cp_async16(bbase + (unsigned)(r * 36 + kq) * 4,
                       B + (size_t)r * K + k0 + kq, 16);
        }
    };
    auto COMP = [&](int stg) {
        const unsigned* a = As + (size_t)stg * TILE_U32;
        const unsigned* b = Bs + (size_t)stg * TILE_U32;
#pragma unroll
        for (int kk = 0; kk < 32; kk += 8) {
            unsigned af[4][4], bf[4][2];
#pragma unroll
            for (int mi = 0; mi < 4; ++mi) {
                int r = wm + mi * 16 + g;
                af[mi][0] = a[r * 36 + kk + tg];
                af[mi][1] = a[(r + 8) * 36 + kk + tg];
                af[mi][2] = a[r * 36 + kk + tg + 4];
                af[mi][3] = a[(r + 8) * 36 + kk + tg + 4];
            }
#pragma unroll
            for (int ni = 0; ni < 4; ++ni) {
                int c = wn + ni * 8 + g;
                bf[ni][0] = b[c * 36 + kk + tg];
                bf[ni][1] = b[c * 36 + kk + tg + 4];
            }
#pragma unroll
            for (int mi = 0; mi < 4; ++mi)
#pragma unroll
                for (int ni = 0; ni < 4; ++ni) {
                    asm volatile(
                        "mma.sync.aligned.m16n8k8.row.col.f32.tf32.tf32.f32 "
                        "{%0,%1,%2,%3}, {%4,%5,%6,%7}, {%8,%9}, {%0,%1,%2,%3};"
                        : "+f"(acc[mi][ni][0]), "+f"(acc[mi][ni][1]),
                          "+f"(acc[mi][ni][2]), "+f"(acc[mi][ni][3])
                        : "r"(af[mi][0]), "r"(af[mi][1]), "r"(af[mi][2]), "r"(af[mi][3]),
                          "r"(bf[ni][0]), "r"(bf[ni][1]));
                }
        }
    };

#pragma unroll
    for (int s = 0; s < NSTAGE - 1; ++s) {
        if (s < numT) GLOAD(s, s);
        CP_COMMIT();
    }
    for (int t = 0; t < numT; ++t) {
        if (t + NSTAGE - 1 < numT) GLOAD((t + NSTAGE - 1) % NSTAGE, t + NSTAGE - 1);
        CP_COMMIT();
        CP_WAIT(NSTAGE - 1);
        __syncthreads();
        COMP(t % NSTAGE);
        __syncthreads();
    }

#pragma unroll
    for (int mi = 0; mi < 4; ++mi) {
        int r0 = m0 + wm + mi * 16 + g;
        int r1 = r0 + 8;
        float d00 = 0.f, d01 = 0.f, d02 = 0.f, d10 = 0.f, d11 = 0.f, d12 = 0.f;
        if (r0 < M) { d00 = deg[(size_t)r0 * 3]; d01 = deg[(size_t)r0 * 3 + 1]; d02 = deg[(size_t)r0 * 3 + 2]; }
        if (r1 < M) { d10 = deg[(size_t)r1 * 3]; d11 = deg[(size_t)r1 * 3 + 1]; d12 = deg[(size_t)r1 * 3 + 2]; }
#pragma unroll
        for (int ni = 0; ni < 4; ++ni) {
            int cl = wn + ni * 8 + tg * 2;
            float e00 = bl3[cl],       e01 = bl3[cl + 1];
            float e10 = bl3[128 + cl], e11 = bl3[129 + cl];
            float e20 = bl3[256 + cl], e21 = bl3[257 + cl];
            float v00 = acc[mi][ni][0] + d00 * e00 + d01 * e10 + d02 * e20;
            float v01 = acc[mi][ni][1] + d00 * e01 + d01 * e11 + d02 * e21;
            float v10 = acc[mi][ni][2] + d10 * e00 + d11 * e10 + d12 * e20;
            float v11 = acc[mi][ni][3] + d10 * e01 + d11 * e11 + d12 * e21;
            if (r0 < M) *(float2*)(C + (size_t)r0 * J + cl) = make_float2(rnd_tf32(v00), rnd_tf32(v01));
            if (r1 < M) *(float2*)(C + (size_t)r1 * J + cl) = make_float2(rnd_tf32(v10), rnd_tf32(v11));
        }
    }
}

// ---------------- paired GEMM + partial gates, continuous cp.async pipeline ----------------
// grid (391, 3): chunk 0 -> r (K=256 over [a|h]); chunk 1 -> z; chunk 2 -> i_n and h_n.
__global__ __launch_bounds__(256, 2) void gemm_pair_kernel(
    const float* __restrict__ abuf, const float* __restrict__ hbuf,
    const float* __restrict__ W_ih_l, const float* __restrict__ W_hh_l,
    const float* __restrict__ b_ih_l, const float* __restrict__ b_hh_l,
    float* __restrict__ rbuf, float* __restrict__ zbuf,
    float* __restrict__ inbuf, float* __restrict__ hnbuf)
{
    extern __shared__ unsigned sm[];
    unsigned* As = sm;
    unsigned* Bs = sm + NSTAGE * TILE_U32;

    const int tid  = threadIdx.x;
    const int warp = tid >> 5;
    const int lane = tid & 31;
    const int g    = lane >> 2;
    const int tg   = lane & 3;
    const int wm   = (warp >> 2) * 64;
    const int wn   = (warp & 3) * 32;
    const int m0   = blockIdx.x * 128;
    const int chunk = blockIdx.y;

    float acc[4][4][4];

    auto CLEAR = [&]() {
#pragma unroll
        for (int mi = 0; mi < 4; ++mi)
#pragma unroll
            for (int ni = 0; ni < 4; ++ni)
#pragma unroll
                for (int q = 0; q < 4; ++q) acc[mi][ni][q] = 0.f;
    };
    // tile-indexed load: tile t in [0,half) from (A1,B1) at k=t*32; t>=half from (A2,B2)
    auto GLOADC = [&](const float* A1, const float* B1,
                      const float* A2, const float* B2, int half, int stg, int t) {
        const float* A = (t < half) ? A1 : A2;
        const float* B = (t < half) ? B1 : B2;
        int k0 = ((t < half) ? t : t - half) << 5;
        unsigned abase = (unsigned)__cvta_generic_to_shared(As + (size_t)stg * TILE_U32);
        unsigned bbase = (unsigned)__cvta_generic_to_shared(Bs + (size_t)stg * TILE_U32);
#pragma unroll
        for (int u = 0; u < 4; ++u) {
            int f  = tid + u * 256;
            int r  = f >> 3;
            int kq = (f & 7) << 2;
            int gm = m0 + r;
            int gmc = gm < NN ? gm : (NN - 1);
            cp_async16(abase + (unsigned)(r * 36 + kq) * 4,
                       A + (size_t)gmc * HD + k0 + kq, gm < NN ? 16 : 0);
            cp_async16(bbase + (unsigned)(r * 36 + kq) * 4,
                       B + (size_t)r * HD + k0 + kq, 16);
        }
    };
    auto COMP = [&](int stg) {
        const unsigned* a = As + (size_t)stg * TILE_U32;
        const unsigned* b = Bs + (size_t)stg * TILE_U32;
#pragma unroll
        for (int kk = 0; kk < 32; kk += 8) {
            unsigned af[4][4], bf[4][2];
#pragma unroll
            for (int mi = 0; mi < 4; ++mi) {
                int r = wm + mi * 16 + g;
                af[mi][0] = a[r * 36 + kk + tg];
                af[mi][1] = a[(r + 8) * 36 + kk + tg];
                af[mi][2] = a[r * 36 + kk + tg + 4];
                af[mi][3] = a[(r + 8) * 36 + kk + tg + 4];
            }
#pragma unroll
            for (int ni = 0; ni < 4; ++ni) {
                int c = wn + ni * 8 + g;
                bf[ni][0] = b[c * 36 + kk + tg];
                bf[ni][1] = b[c * 36 + kk + tg + 4];
            }
#pragma unroll
            for (int mi = 0; mi < 4; ++mi)
#pragma unroll
                for (int ni = 0; ni < 4; ++ni) {
                    asm volatile(
                        "mma.sync.aligned.m16n8k8.row.col.f32.tf32.tf32.f32 "
                        "{%0,%1,%2,%3}, {%4,%5,%6,%7}, {%8,%9}, {%0,%1,%2,%3};"
                        : "+f"(acc[mi][ni][0]), "+f"(acc[mi][ni][1]),
                          "+f"(acc[mi][ni][2]), "+f"(acc[mi][ni][3])
                        : "r"(af[mi][0]), "r"(af[mi][1]), "r"(af[mi][2]), "r"(af[mi][3]),
                          "r"(bf[ni][0]), "r"(bf[ni][1]));
                }
        }
    };
    auto RUNCAT = [&](const float* A1, const float* B1,
                      const float* A2, const float* B2, int half, int numT) {
#pragma unroll
        for (int s = 0; s < NSTAGE - 1; ++s) {
            if (s < numT) GLOADC(A1, B1, A2, B2, half, s, s);
            CP_COMMIT();
        }
        for (int t = 0; t < numT; ++t) {
            if (t + NSTAGE - 1 < numT)
                GLOADC(A1, B1, A2, B2, half, (t + NSTAGE - 1) % NSTAGE, t + NSTAGE - 1);
            CP_COMMIT();
            CP_WAIT(NSTAGE - 1);
            __syncthreads();
            COMP(t % NSTAGE);
            __syncthreads();
        }
    };
    auto STORE_EPI = [&](float* __restrict__ out, const float* __restrict__ bias0,
                         const float* __restrict__ bias1, bool sig) {
#pragma unroll
        for (int mi = 0; mi < 4; ++mi) {
            int r0 = m0 + wm + mi * 16 + g;
            int r1 = r0 + 8;
#pragma unroll
            for (int ni = 0; ni < 4; ++ni) {
                int cl = wn + ni * 8 + tg * 2;
                float bb0 = bias0[cl], bb1 = bias0[cl + 1];
                if (bias1) { bb0 += bias1[cl]; bb1 += bias1[cl + 1]; }
                float v00 = acc[mi][ni][0] + bb0, v01 = acc[mi][ni][1] + bb1;
                float v10 = acc[mi][ni][2] + bb0, v11 = acc[mi][ni][3] + bb1;
                if (sig) {
                    v00 = 1.f / (1.f + expf(-v00));
                    v01 = 1.f / (1.f + expf(-v01));
                    v10 = 1.f / (1.f + expf(-v10));
                    v11 = 1.f / (1.f + expf(-v11));
                }
                if (r0 < NN) *(float2*)(out + (size_t)r0 * HD + cl) = make_float2(v00, v01);
                if (r1 < NN) *(float2*)(out + (size_t)r1 * HD + cl) = make_float2(v10, v11);
            }
        }
    };

    if (chunk < 2) {
        CLEAR();
        // one continuous K=256 pipeline: tiles 0-3 from (a, W_ih), 4-7 from (h, W_hh)
        RUNCAT(abuf, W_ih_l + (size_t)chunk * 128 * HD,
               hbuf, W_hh_l + (size_t)chunk * 128 * HD, 4, 8);
        STORE_EPI(chunk == 0 ? rbuf : zbuf,
                  b_ih_l + chunk * 128, b_hh_l + chunk * 128, true);
    } else {
        CLEAR();
        RUNCAT(abuf, W_ih_l + (size_t)256 * HD, abuf, W_ih_l + (size_t)256 * HD, 4, 4);
        STORE_EPI(inbuf, b_ih_l + 256, nullptr, false);
        CLEAR();
        RUNCAT(hbuf, W_hh_l + (size_t)256 * HD, hbuf, W_hh_l + (size_t)256 * HD, 4, 4);
        STORE_EPI(hnbuf, b_hh_l + 256, nullptr, false);
    }
}

// ---------------- final gates: h = (1-z)*tanh(i_n + r*h_n) + z*h; also h32 -------------
__global__ void gates_kernel(const float* __restrict__ rbuf, const float* __restrict__ zbuf,
                             const float* __restrict__ inbuf, const float* __restrict__ hnbuf,
                             float* __restrict__ h, float* __restrict__ h32) {
    int idx = blockIdx.x * blockDim.x + threadIdx.x;
    if (idx >= NN * HD) return;
    float r = rbuf[idx], z = zbuf[idx];
    float nc = tanhf(inbuf[idx] + r * hnbuf[idx]);
    float nh = (1.f - z) * nc + z * h[idx];
    h[idx] = nh;
    h32[idx] = rnd_tf32(nh);
}

// ---------------- head ----------------
__global__ void head_kernel(const float* __restrict__ agg, const float* __restrict__ W1,
                            const float* __restrict__ b1, const float* __restrict__ W2,
                            const float* __restrict__ b2, float* __restrict__ out,
                            int out_size) {
    int g = blockIdx.x;
    int o = threadIdx.x; // 128
    __shared__ float sa[K3];
    __shared__ float sx[HD];
    for (int k = o; k < K3; k += HD) sa[k] = agg[g * K3 + k];
    __syncthreads();
    float acc = b1[o];
    for (int k = 0; k < K3; ++k) acc += sa[k] * W1[k * HD + o];
    acc = fmaxf(acc, 0.f);
    sx[o] = acc * W2[o];
    __syncthreads();
    for (int st = 64; st > 0; st >>= 1) {
        if (o < st) sx[o] += sx[o + st];
        __syncthreads();
    }
    if (o == 0 && g < out_size) out[g] = sx[0] + b2[0];
    for (int k = o; k < K3; k += HD) {
        int oi = NG + g * K3 + k;
        if (oi < out_size) out[oi] = sa[k];
    }
}

// ---------------- host launch ----------------
extern "C" void kernel_launch(void* const* d_in, const int* in_sizes, int n_in,
                              void* d_out, int out_size) {
    const int*   text_idx = (const int*)d_in[0];
    const int*   src      = (const int*)d_in[1];
    const int*   dst      = (const int*)d_in[2];
    const int*   etype    = (const int*)d_in[3];
    const int*   graph_id = (const int*)d_in[4];
    const float* emb      = (const float*)d_in[5];
    const float* Wl       = (const float*)d_in[6];
    const float* bl       = (const float*)d_in[7];
    const float* W_ih     = (const float*)d_in[8];
    const float* W_hh     = (const float*)d_in[9];
    const float* b_ih     = (const float*)d_in[10];
    const float* b_hh     = (const float*)d_in[11];
    const float* W1       = (const float*)d_in[12];
    const float* b1       = (const float*)d_in[13];
    const float* W2       = (const float*)d_in[14];
    const float* b2       = (const float*)d_in[15];
    float* out = (float*)d_out;

    float *h, *S, *a, *gi, *gh, *deg, *wcatT, *wih32, *whh32, *agg;
    int *cnt, *rowptr, *cursor, *edges, *goff;
    cudaGetSymbolAddress((void**)&h,      d_h);
    cudaGetSymbolAddress((void**)&S,      d_S);
    cudaGetSymbolAddress((void**)&a,      d_a);
    cudaGetSymbolAddress((void**)&gi,     d_gi);
    cudaGetSymbolAddress((void**)&gh,     d_gh);
    cudaGetSymbolAddress((void**)&deg,    d_deg);
    cudaGetSymbolAddress((void**)&wcatT,  d_wcatT);
    cudaGetSymbolAddress((void**)&wih32,  d_wih32);
    cudaGetSymbolAddress((void**)&whh32,  d_whh32);
    cudaGetSymbolAddress((void**)&agg,    d_agg);
    cudaGetSymbolAddress((void**)&cnt,    d_cnt);
    cudaGetSymbolAddress((void**)&rowptr, d_rowptr);
    cudaGetSymbolAddress((void**)&cursor, d_cursor);
    cudaGetSymbolAddress((void**)&edges,  d_edges);
    cudaGetSymbolAddress((void**)&goff,   d_goff);

    float* rbuf  = gi;
    float* zbuf  = gi + (size_t)NN * HD;
    float* inbuf = gi + (size_t)2 * NN * HD;
    float* hnbuf = gh;
    float* h32   = gh + (size_t)NN * HD;

    static bool attr_set = false;
    if (!attr_set) {
        cudaFuncSetAttribute(tf32gemm_abt_kernel,
                             cudaFuncAttributeMaxDynamicSharedMemorySize, GEMM_SMEM_BYTES);
        cudaFuncSetAttribute(gemm_pair_kernel,
                             cudaFuncAttributeMaxDynamicSharedMemorySize, GEMM_SMEM_BYTES);
        cudaFuncSetAttribute(scan_goff_kernel,
                             cudaFuncAttributeMaxDynamicSharedMemorySize, SCAN_SMEM);
        attr_set = true;
    }

    // ---- setup: 4 launches (cnt zeroed by previous replay's scan; zero-init at load) ----
    count_edges_kernel<<<(NE + 255) / 256, 256>>>(dst, cnt);
    scan_goff_kernel<<<1, 1024, SCAN_SMEM>>>(cnt, rowptr, cursor, graph_id, goff);
    place_edges_kernel<<<(NE + 255) / 256, 256>>>(src, dst, etype, cursor, edges);
    embed_weights_kernel<<<(NN * HD + 255) / 256, 256>>>(
        text_idx, emb, h, h32, Wl, wcatT, W_ih, W_hh, wih32, whh32);

    const dim3 g1((NN + 127) / 128, 1);
    const dim3 gp((NN + 127) / 128, 3);

    for (int l = 0; l < NLAYERS; ++l) {
        for (int s = 0; s < NSTEPS; ++s) {
            aggregate_kernel<<<(NN * 32 + 255) / 256, 256>>>(h, rowptr, edges, S, deg);
            tf32gemm_abt_kernel<<<g1, 256, GEMM_SMEM_BYTES>>>(
                S, wcatT + (size_t)l * HD * K3, a,
                NN, K3, HD, deg, bl + l * K3);
            gemm_pair_kernel<<<gp, 256, GEMM_SMEM_BYTES>>>(
                a, h32,
                wih32 + (size_t)l * K3 * HD, whh32 + (size_t)l * K3 * HD,
                b_ih + l * K3, b_hh + l * K3,
                rbuf, zbuf, inbuf, hnbuf);
            gates_kernel<<<(NN * HD + 255) / 256, 256>>>(rbuf, zbuf, inbuf, hnbuf, h, h32);
        }
        mean_kernel<<<NG, HD>>>(h, goff, agg, l + 1);
    }

    mean0_emb_kernel<<<NG, HD>>>(text_idx, emb, goff, agg);
    head_kernel<<<NG, HD>>>(agg, W1, b1, W2, b2, out, out_size);
}

// round 12
// speedup vs baseline: 1.0069x; 1.0069x over previous
#include <cuda_runtime.h>
#include <math.h>
#include <stdint.h>

// ---------------- problem constants ----------------
#define NN 50000         // nodes
#define NE 600000        // edges
#define HD 128           // hidden
#define NG 64            // graphs
#define K3 384           // 3*H
#define NLAYERS 2
#define NSTEPS 2
#define NSTAGE 3

// ---------------- device scratch (no allocs; zero-initialized at load) ----------------
__device__ float d_h[(size_t)NN * HD];
__device__ float d_S[(size_t)NN * K3];
__device__ float d_a[(size_t)NN * HD];
__device__ float d_gi[(size_t)NN * K3];   // planes: r | z | i_n
__device__ float d_gh[(size_t)NN * K3];   // planes: h_n | h32 (rounded h copy)
__device__ float d_deg[(size_t)NN * 3];
__device__ int   d_cnt[NN];               // zeroed by scan kernel after use (replay-safe)
__device__ int   d_rowptr[NN + 1];
__device__ int   d_cursor[NN];
__device__ int   d_edges[NE];
__device__ int   d_goff[NG + 1];
__device__ float d_wcatT[2 * HD * K3];    // per layer: [128 out][384 k], tf32-rounded
__device__ float d_wih32[2 * K3 * HD];    // tf32-rounded W_ih
__device__ float d_whh32[2 * K3 * HD];    // tf32-rounded W_hh
__device__ float d_agg[NG * K3];

__device__ __forceinline__ unsigned cvt_tf32(float x) {
    unsigned r;
    asm("cvt.rna.tf32.f32 %0, %1;" : "=r"(r) : "f"(x));
    return r;
}
__device__ __forceinline__ float rnd_tf32(float x) {
    return __uint_as_float(cvt_tf32(x));
}
__device__ __forceinline__ void f4add(float4& a, const float4& b) {
    a.x += b.x; a.y += b.y; a.z += b.z; a.w += b.w;
}
__device__ __forceinline__ void cp_async16(unsigned saddr, const void* gptr, int szbytes) {
    asm volatile("cp.async.cg.shared.global [%0], [%1], 16, %2;"
                 :: "r"(saddr), "l"(gptr), "r"(szbytes));
}
#define CP_COMMIT() asm volatile("cp.async.commit_group;")
#define CP_WAIT(n)  asm volatile("cp.async.wait_group %0;" :: "n"(n))

// ---------------- setup kernels ----------------

__global__ void count_edges_kernel(const int* __restrict__ dst, int* __restrict__ cnt) {
    int e = blockIdx.x * blockDim.x + threadIdx.x;
    if (e < NE) atomicAdd(&cnt[dst[e]], 1);
}

// coalesced scan: stage counts in smem, chunk-scan, zero cnt for next replay; fuse goff.
#define SCAN_SMEM (NN * 4)
__global__ void scan_goff_kernel(int* __restrict__ cnt, int* __restrict__ rowptr,
                                 int* __restrict__ cursor,
                                 const int* __restrict__ graph_id, int* __restrict__ goff) {
    extern __shared__ int sc[];
    const int CH = (NN + 1023) / 1024;   // 49
    int tid = threadIdx.x;

    // coalesced stage-in + zero for next replay
    for (int q = 0; q < CH; ++q) {
        int i = q * 1024 + tid;
        if (i < NN) { sc[i] = cnt[i]; cnt[i] = 0; }
    }
    __syncthreads();

    int s = tid * CH;
    int e = s + CH < NN ? s + CH : NN;
    int sum = 0;
    for (int i = s; i < e; ++i) sum += sc[i];

    __shared__ int warpsums[32];
    int lane = tid & 31, wid = tid >> 5;
    int v = sum;
#pragma unroll
    for (int off = 1; off < 32; off <<= 1) {
        int t = __shfl_up_sync(0xFFFFFFFFu, v, off);
        if (lane >= off) v += t;
    }
    if (lane == 31) warpsums[wid] = v;
    __syncthreads();
    if (wid == 0) {
        int w = warpsums[lane];
#pragma unroll
        for (int off = 1; off < 32; off <<= 1) {
            int t = __shfl_up_sync(0xFFFFFFFFu, w, off);
            if (lane >= off) w += t;
        }
        warpsums[lane] = w;
    }
    __syncthreads();
    int run = (v - sum) + (wid > 0 ? warpsums[wid - 1] : 0);
    for (int i = s; i < e; ++i) {
        int c = sc[i];
        cursor[i] = run;
        run += c;
        rowptr[i + 1] = run;
    }
    if (tid == 0) rowptr[0] = 0;

    // goff: graph_id sorted -> lower_bound
    if (tid <= NG) {
        if (tid == NG) goff[NG] = NN;
        else {
            int lo = 0, hi = NN;
            while (lo < hi) {
                int mid = (lo + hi) >> 1;
                if (graph_id[mid] < tid) lo = mid + 1; else hi = mid;
            }
            goff[tid] = lo;
        }
    }
}

__global__ void place_edges_kernel(const int* __restrict__ src, const int* __restrict__ dst,
                                   const int* __restrict__ etype, int* __restrict__ cursor,
                                   int* __restrict__ edges) {
    int e = blockIdx.x * blockDim.x + threadIdx.x;
    if (e >= NE) return;
    int d = dst[e];
    int pos = atomicAdd(&cursor[d], 1);
    edges[pos] = src[e] | (etype[e] << 24);
}

// embed (h + rounded h32) + Wl transpose/round + W_ih/W_hh round — all pure copies
__global__ void embed_weights_kernel(const int* __restrict__ text_idx,
                                     const float* __restrict__ emb,
                                     float* __restrict__ h, float* __restrict__ h32,
                                     const float* __restrict__ Wl, float* __restrict__ wcatT,
                                     const float* __restrict__ Wih, const float* __restrict__ Whh,
                                     float* __restrict__ wih32, float* __restrict__ whh32) {
    int idx = blockIdx.x * blockDim.x + threadIdx.x;
    if (idx < 2 * 3 * 128 * 128) {
        int o  = idx & 127;
        int hh = (idx >> 7) & 127;
        int lt = idx >> 14;
        int t  = lt % 3;
        int l  = lt / 3;
        wcatT[(size_t)l * HD * K3 + (size_t)o * K3 + t * 128 + hh] = rnd_tf32(Wl[idx]);
    }
    if (idx < 2 * K3 * HD) {
        wih32[idx] = rnd_tf32(Wih[idx]);
        whh32[idx] = rnd_tf32(Whh[idx]);
    }
    if (idx < NN * HD) {
        int n = idx >> 7, c = idx & 127;
        float v = emb[(size_t)text_idx[n] * HD + c];
        h[idx] = v;
        h32[idx] = rnd_tf32(v);
    }
}

// segment mean of current h -> agg slot
__global__ void mean_kernel(const float* __restrict__ h, const int* __restrict__ goff,
                            float* __restrict__ agg, int slot) {
    int g = blockIdx.x;
    int c = threadIdx.x; // 128
    int s = goff[g], e = goff[g + 1];
    float a0 = 0.f, a1 = 0.f, a2 = 0.f, a3 = 0.f;
    int r = s;
    for (; r + 4 <= e; r += 4) {
        a0 += h[(size_t)(r + 0) * HD + c];
        a1 += h[(size_t)(r + 1) * HD + c];
        a2 += h[(size_t)(r + 2) * HD + c];
        a3 += h[(size_t)(r + 3) * HD + c];
    }
    for (; r < e; ++r) a0 += h[(size_t)r * HD + c];
    float acc = (a0 + a1) + (a2 + a3);
    float cntf = (float)((e - s) > 0 ? (e - s) : 1);
    agg[g * K3 + slot * HD + c] = acc / cntf;
}

// slot-0 mean recomputed from emb[text_idx] (order-free)
__global__ void mean0_emb_kernel(const int* __restrict__ text_idx,
                                 const float* __restrict__ emb,
                                 const int* __restrict__ goff,
                                 float* __restrict__ agg) {
    int g = blockIdx.x;
    int c = threadIdx.x; // 128
    int s = goff[g], e = goff[g + 1];
    float a0 = 0.f, a1 = 0.f, a2 = 0.f, a3 = 0.f;
    int r = s;
    for (; r + 4 <= e; r += 4) {
        a0 += emb[(size_t)text_idx[r + 0] * HD + c];
        a1 += emb[(size_t)text_idx[r + 1] * HD + c];
        a2 += emb[(size_t)text_idx[r + 2] * HD + c];
        a3 += emb[(size_t)text_idx[r + 3] * HD + c];
    }
    for (; r < e; ++r) a0 += emb[(size_t)text_idx[r] * HD + c];
    float acc = (a0 + a1) + (a2 + a3);
    float cntf = (float)((e - s) > 0 ? (e - s) : 1);
    agg[g * K3 + c] = acc / cntf;
}

// one warp per dst node: per-etype sums -> S pre-rounded to tf32
__global__ void aggregate_kernel(const float* __restrict__ h, const int* __restrict__ rowptr,
                                 const int* __restrict__ edges, float* __restrict__ S,
                                 float* __restrict__ deg) {
    int warp = (blockIdx.x * blockDim.x + threadIdx.x) >> 5;
    int lane = threadIdx.x & 31;
    if (warp >= NN) return;
    int s = rowptr[warp], e = rowptr[warp + 1];
    float4 a0 = {0,0,0,0}, a1 = {0,0,0,0}, a2 = {0,0,0,0};
    int c0 = 0, c1 = 0, c2 = 0;
    const float4* h4 = (const float4*)h;
    for (int i = s; i < e; ++i) {
        int p = edges[i];
        int srcn = p & 0xFFFFFF;
        int t = p >> 24;
        float4 v = h4[(size_t)srcn * 32 + lane];
        if (t == 0)      { f4add(a0, v); c0++; }
        else if (t == 1) { f4add(a1, v); c1++; }
        else             { f4add(a2, v); c2++; }
    }
    uint4* S4 = (uint4*)S;
    size_t base = (size_t)warp * 96;
    S4[base + lane]      = make_uint4(cvt_tf32(a0.x), cvt_tf32(a0.y), cvt_tf32(a0.z), cvt_tf32(a0.w));
    S4[base + 32 + lane] = make_uint4(cvt_tf32(a1.x), cvt_tf32(a1.y), cvt_tf32(a1.z), cvt_tf32(a1.w));
    S4[base + 64 + lane] = make_uint4(cvt_tf32(a2.x), cvt_tf32(a2.y), cvt_tf32(a2.z), cvt_tf32(a2.w));
    if (lane == 0) {
        deg[(size_t)warp * 3 + 0] = (float)c0;
        deg[(size_t)warp * 3 + 1] = (float)c1;
        deg[(size_t)warp * 3 + 2] = (float)c2;
    }
}

// ---------------- TF32 GEMM, cp.async 3-stage pipeline ----------------
#define TILE_U32   (128 * 36)
#define GEMM_SMEM_BYTES (NSTAGE * TILE_U32 * 2 * 4)

// C[m][j] = sum_k A[m][k]*B[j][k]; +deg-weighted bl3 epilogue; output rounded to tf32
__global__ __launch_bounds__(256, 2) void tf32gemm_abt_kernel(
    const float* __restrict__ A, const float* __restrict__ B, float* __restrict__ C,
    int M, int K, int J,
    const float* __restrict__ deg, const float* __restrict__ bl3)
{
    extern __shared__ unsigned sm[];
    unsigned* As = sm;
    unsigned* Bs = sm + NSTAGE * TILE_U32;

    const int tid = threadIdx.x;
    const int warp = tid >> 5;
    const int lane = tid & 31;
    const int g    = lane >> 2;
    const int tg   = lane & 3;
    const int wm   = (warp >> 2) * 64;
    const int wn   = (warp & 3) * 32;
    const int m0   = blockIdx.x * 128;

    float acc[4][4][4];
#pragma unroll
    for (int mi = 0; mi < 4; ++mi)
#pragma unroll
        for (int ni = 0; ni < 4; ++ni)
#pragma unroll
            for (int q = 0; q < 4; ++q) acc[mi][ni][q] = 0.f;

    const int numT = K >> 5;

    auto GLOAD = [&](int stg, int t) {
        int k0 = t << 5;
        unsigned abase = (unsigned)__cvta_generic_to_shared(As + (size_t)stg * TILE_U32);
        unsigned bbase = (unsigned)__cvta_generic_to_shared(Bs + (size_t)stg * TILE_U32);
#pragma unroll
        for (int u = 0; u < 4; ++u) {
            int f  = tid + u * 256;
            int r  = f >> 3;
            int kq = (f & 7) << 2;
            int gm = m0 + r;
            int gmc = gm < M ? gm : (M - 1);
            cp_async16(abase + (unsigned)(r * 36 + kq) * 4,
                       A + (size_t)gmc * K + k0 + kq, gm < M ? 16 : 0);
            cp_async16(bbase + (unsigned)(r * 36 + kq) * 4,
                       B + (size_t)r * K + k0 + kq, 16);
        }
    };
    auto COMP = [&](int stg) {
        const unsigned* a = As + (size_t)stg * TILE_U32;
        const unsigned* b = Bs + (size_t)stg * TILE_U32;
#pragma unroll
        for (int kk = 0; kk < 32; kk += 8) {
            unsigned af[4][4], bf[4][2];
#pragma unroll
            for (int mi = 0; mi < 4; ++mi) {
                int r = wm + mi * 16 + g;
                af[mi][0] = a[r * 36 + kk + tg];
                af[mi][1] = a[(r + 8) * 36 + kk + tg];
                af[mi][2] = a[r * 36 + kk + tg + 4];
                af[mi][3] = a[(r + 8) * 36 + kk + tg + 4];
            }
#pragma unroll
            for (int ni = 0; ni < 4; ++ni) {
                int c = wn + ni * 8 + g;
                bf[ni][0] = b[c * 36 + kk + tg];
                bf[ni][1] = b[c * 36 + kk + tg + 4];
            }
#pragma unroll
            for (int mi = 0; mi < 4; ++mi)
#pragma unroll
                for (int ni = 0; ni < 4; ++ni) {
                    asm volatile(
                        "mma.sync.aligned.m16n8k8.row.col.f32.tf32.tf32.f32 "
                        "{%0,%1,%2,%3}, {%4,%5,%6,%7}, {%8,%9}, {%0,%1,%2,%3};"
                        : "+f"(acc[mi][ni][0]), "+f"(acc[mi][ni][1]),
                          "+f"(acc[mi][ni][2]), "+f"(acc[mi][ni][3])
                        : "r"(af[mi][0]), "r"(af[mi][1]), "r"(af[mi][2]), "r"(af[mi][3]),
                          "r"(bf[ni][0]), "r"(bf[ni][1]));
                }
        }
    };

#pragma unroll
    for (int s = 0; s < NSTAGE - 1; ++s) {
        if (s < numT) GLOAD(s, s);
        CP_COMMIT();
    }
    for (int t = 0; t < numT; ++t) {
        if (t + NSTAGE - 1 < numT) GLOAD((t + NSTAGE - 1) % NSTAGE, t + NSTAGE - 1);
        CP_COMMIT();
        CP_WAIT(NSTAGE - 1);
        __syncthreads();
        COMP(t % NSTAGE);
        __syncthreads();
    }

#pragma unroll
    for (int mi = 0; mi < 4; ++mi) {
        int r0 = m0 + wm + mi * 16 + g;
        int r1 = r0 + 8;
        float d00 = 0.f, d01 = 0.f, d02 = 0.f, d10 = 0.f, d11 = 0.f, d12 = 0.f;
        if (r0 < M) { d00 = deg[(size_t)r0 * 3]; d01 = deg[(size_t)r0 * 3 + 1]; d02 = deg[(size_t)r0 * 3 + 2]; }
        if (r1 < M) { d10 = deg[(size_t)r1 * 3]; d11 = deg[(size_t)r1 * 3 + 1]; d12 = deg[(size_t)r1 * 3 + 2]; }
#pragma unroll
        for (int ni = 0; ni < 4; ++ni) {
            int cl = wn + ni * 8 + tg * 2;
            float e00 = bl3[cl],       e01 = bl3[cl + 1];
            float e10 = bl3[128 + cl], e11 = bl3[129 + cl];
            float e20 = bl3[256 + cl], e21 = bl3[257 + cl];
            float v00 = acc[mi][ni][0] + d00 * e00 + d01 * e10 + d02 * e20;
            float v01 = acc[mi][ni][1] + d00 * e01 + d01 * e11 + d02 * e21;
            float v10 = acc[mi][ni][2] + d10 * e00 + d11 * e10 + d12 * e20;
            float v11 = acc[mi][ni][3] + d10 * e01 + d11 * e11 + d12 * e21;
            if (r0 < M) *(float2*)(C + (size_t)r0 * J + cl) = make_float2(rnd_tf32(v00), rnd_tf32(v01));
            if (r1 < M) *(float2*)(C + (size_t)r1 * J + cl) = make_float2(rnd_tf32(v10), rnd_tf32(v11));
        }
    }
}

// ---------------- paired GEMM + partial gates (R9 version: unrolled 4-tile pipelines) ----
// grid (391, 3): chunk 0 -> r; chunk 1 -> z; chunk 2 -> i_n and h_n.
__global__ __launch_bounds__(256, 2) void gemm_pair_kernel(
    const float* __restrict__ abuf, const float* __restrict__ hbuf,
    const float* __restrict__ W_ih_l, const float* __restrict__ W_hh_l,
    const float* __restrict__ b_ih_l, const float* __restrict__ b_hh_l,
    float* __restrict__ rbuf, float* __restrict__ zbuf,
    float* __restrict__ inbuf, float* __restrict__ hnbuf)
{
    extern __shared__ unsigned sm[];
    unsigned* As = sm;
    unsigned* Bs = sm + NSTAGE * TILE_U32;

    const int tid  = threadIdx.x;
    const int warp = tid >> 5;
    const int lane = tid & 31;
    const int g    = lane >> 2;
    const int tg   = lane & 3;
    const int wm   = (warp >> 2) * 64;
    const int wn   = (warp & 3) * 32;
    const int m0   = blockIdx.x * 128;
    const int chunk = blockIdx.y;

    float acc[4][4][4];

    auto CLEAR = [&]() {
#pragma unroll
        for (int mi = 0; mi < 4; ++mi)
#pragma unroll
            for (int ni = 0; ni < 4; ++ni)
#pragma unroll
                for (int q = 0; q < 4; ++q) acc[mi][ni][q] = 0.f;
    };
    auto GLOAD = [&](const float* __restrict__ A, const float* __restrict__ B, int stg, int t) {
        int k0 = t << 5;
        unsigned abase = (unsigned)__cvta_generic_to_shared(As + (size_t)stg * TILE_U32);
        unsigned bbase = (unsigned)__cvta_generic_to_shared(Bs + (size_t)stg * TILE_U32);
#pragma unroll
        for (int u = 0; u < 4; ++u) {
            int f  = tid + u * 256;
            int r  = f >> 3;
            int kq = (f & 7) << 2;
            int gm = m0 + r;
            int gmc = gm < NN ? gm : (NN - 1);
            cp_async16(abase + (unsigned)(r * 36 + kq) * 4,
                       A + (size_t)gmc * HD + k0 + kq, gm < NN ? 16 : 0);
            cp_async16(bbase + (unsigned)(r * 36 + kq) * 4,
                       B + (size_t)r * HD + k0 + kq, 16);
        }
    };
    auto COMP = [&](int stg) {
        const unsigned* a = As + (size_t)stg * TILE_U32;
        const unsigned* b = Bs + (size_t)stg * TILE_U32;
#pragma unroll
        for (int kk = 0; kk < 32; kk += 8) {
            unsigned af[4][4], bf[4][2];
#pragma unroll
            for (int mi = 0; mi < 4; ++mi) {
                int r = wm + mi * 16 + g;
                af[mi][0] = a[r * 36 + kk + tg];
                af[mi][1] = a[(r + 8) * 36 + kk + tg];
                af[mi][2] = a[r * 36 + kk + tg + 4];
                af[mi][3] = a[(r + 8) * 36 + kk + tg + 4];
            }
#pragma unroll
            for (int ni = 0; ni < 4; ++ni) {
                int c = wn + ni * 8 + g;
                bf[ni][0] = b[c * 36 + kk + tg];
                bf[ni][1] = b[c * 36 + kk + tg + 4];
            }
#pragma unroll
            for (int mi = 0; mi < 4; ++mi)
#pragma unroll
                for (int ni = 0; ni < 4; ++ni) {
                    asm volatile(
                        "mma.sync.aligned.m16n8k8.row.col.f32.tf32.tf32.f32 "
                        "{%0,%1,%2,%3}, {%4,%5,%6,%7}, {%8,%9}, {%0,%1,%2,%3};"
                        : "+f"(acc[mi][ni][0]), "+f"(acc[mi][ni][1]),
                          "+f"(acc[mi][ni][2]), "+f"(acc[mi][ni][3])
                        : "r"(af[mi][0]), "r"(af[mi][1]), "r"(af[mi][2]), "r"(af[mi][3]),
                          "r"(bf[ni][0]), "r"(bf[ni][1]));
                }
        }
    };
    auto RUN = [&](const float* __restrict__ A, const float* __restrict__ B) {
        const int numT = 4;
#pragma unroll
        for (int s = 0; s < NSTAGE - 1; ++s) {
            GLOAD(A, B, s, s);
            CP_COMMIT();
        }
#pragma unroll
        for (int t = 0; t < numT; ++t) {
            if (t + NSTAGE - 1 < numT) GLOAD(A, B, (t + NSTAGE - 1) % NSTAGE, t + NSTAGE - 1);
            CP_COMMIT();
            CP_WAIT(NSTAGE - 1);
            __syncthreads();
            COMP(t % NSTAGE);
            __syncthreads();
        }
    };
    auto STORE_EPI = [&](float* __restrict__ out, const float* __restrict__ bias0,
                         const float* __restrict__ bias1, bool sig) {
#pragma unroll
        for (int mi = 0; mi < 4; ++mi) {
            int r0 = m0 + wm + mi * 16 + g;
            int r1 = r0 + 8;
#pragma unroll
            for (int ni = 0; ni < 4; ++ni) {
                int cl = wn + ni * 8 + tg * 2;
                float bb0 = bias0[cl], bb1 = bias0[cl + 1];
                if (bias1) { bb0 += bias1[cl]; bb1 += bias1[cl + 1]; }
                float v00 = acc[mi][ni][0] + bb0, v01 = acc[mi][ni][1] + bb1;
                float v10 = acc[mi][ni][2] + bb0, v11 = acc[mi][ni][3] + bb1;
                if (sig) {
                    v00 = 1.f / (1.f + expf(-v00));
                    v01 = 1.f / (1.f + expf(-v01));
                    v10 = 1.f / (1.f + expf(-v10));
                    v11 = 1.f / (1.f + expf(-v11));
                }
                if (r0 < NN) *(float2*)(out + (size_t)r0 * HD + cl) = make_float2(v00, v01);
                if (r1 < NN) *(float2*)(out + (size_t)r1 * HD + cl) = make_float2(v10, v11);
            }
        }
    };

    if (chunk < 2) {
        CLEAR();
        RUN(abuf, W_ih_l + (size_t)chunk * 128 * HD);
        RUN(hbuf, W_hh_l + (size_t)chunk * 128 * HD);
        STORE_EPI(chunk == 0 ? rbuf : zbuf,
                  b_ih_l + chunk * 128, b_hh_l + chunk * 128, true);
    } else {
        CLEAR();
        RUN(abuf, W_ih_l + (size_t)256 * HD);
        STORE_EPI(inbuf, b_ih_l + 256, nullptr, false);
        CLEAR();
        RUN(hbuf, W_hh_l + (size_t)256 * HD);
        STORE_EPI(hnbuf, b_hh_l + 256, nullptr, false);
    }
}

// ---------------- final gates: h = (1-z)*tanh(i_n + r*h_n) + z*h; also h32 -------------
__global__ void gates_kernel(const float* __restrict__ rbuf, const float* __restrict__ zbuf,
                             const float* __restrict__ inbuf, const float* __restrict__ hnbuf,
                             float* __restrict__ h, float* __restrict__ h32) {
    int idx = blockIdx.x * blockDim.x + threadIdx.x;
    if (idx >= NN * HD) return;
    float r = rbuf[idx], z = zbuf[idx];
    float nc = tanhf(inbuf[idx] + r * hnbuf[idx]);
    float nh = (1.f - z) * nc + z * h[idx];
    h[idx] = nh;
    h32[idx] = rnd_tf32(nh);
}

// ---------------- head ----------------
__global__ void head_kernel(const float* __restrict__ agg, const float* __restrict__ W1,
                            const float* __restrict__ b1, const float* __restrict__ W2,
                            const float* __restrict__ b2, float* __restrict__ out,
                            int out_size) {
    int g = blockIdx.x;
    int o = threadIdx.x; // 128
    __shared__ float sa[K3];
    __shared__ float sx[HD];
    for (int k = o; k < K3; k += HD) sa[k] = agg[g * K3 + k];
    __syncthreads();
    float acc = b1[o];
    for (int k = 0; k < K3; ++k) acc += sa[k] * W1[k * HD + o];
    acc = fmaxf(acc, 0.f);
    sx[o] = acc * W2[o];
    __syncthreads();
    for (int st = 64; st > 0; st >>= 1) {
        if (o < st) sx[o] += sx[o + st];
        __syncthreads();
    }
    if (o == 0 && g < out_size) out[g] = sx[0] + b2[0];
    for (int k = o; k < K3; k += HD) {
        int oi = NG + g * K3 + k;
        if (oi < out_size) out[oi] = sa[k];
    }
}

// ---------------- host launch ----------------
extern "C" void kernel_launch(void* const* d_in, const int* in_sizes, int n_in,
                              void* d_out, int out_size) {
    const int*   text_idx = (const int*)d_in[0];
    const int*   src      = (const int*)d_in[1];
    const int*   dst      = (const int*)d_in[2];
    const int*   etype    = (const int*)d_in[3];
    const int*   graph_id = (const int*)d_in[4];
    const float* emb      = (const float*)d_in[5];
    const float* Wl       = (const float*)d_in[6];
    const float* bl       = (const float*)d_in[7];
    const float* W_ih     = (const float*)d_in[8];
    const float* W_hh     = (const float*)d_in[9];
    const float* b_ih     = (const float*)d_in[10];
    const float* b_hh     = (const float*)d_in[11];
    const float* W1       = (const float*)d_in[12];
    const float* b1       = (const float*)d_in[13];
    const float* W2       = (const float*)d_in[14];
    const float* b2       = (const float*)d_in[15];
    float* out = (float*)d_out;

    float *h, *S, *a, *gi, *gh, *deg, *wcatT, *wih32, *whh32, *agg;
    int *cnt, *rowptr, *cursor, *edges, *goff;
    cudaGetSymbolAddress((void**)&h,      d_h);
    cudaGetSymbolAddress((void**)&S,      d_S);
    cudaGetSymbolAddress((void**)&a,      d_a);
    cudaGetSymbolAddress((void**)&gi,     d_gi);
    cudaGetSymbolAddress((void**)&gh,     d_gh);
    cudaGetSymbolAddress((void**)&deg,    d_deg);
    cudaGetSymbolAddress((void**)&wcatT,  d_wcatT);
    cudaGetSymbolAddress((void**)&wih32,  d_wih32);
    cudaGetSymbolAddress((void**)&whh32,  d_whh32);
    cudaGetSymbolAddress((void**)&agg,    d_agg);
    cudaGetSymbolAddress((void**)&cnt,    d_cnt);
    cudaGetSymbolAddress((void**)&rowptr, d_rowptr);
    cudaGetSymbolAddress((void**)&cursor, d_cursor);
    cudaGetSymbolAddress((void**)&edges,  d_edges);
    cudaGetSymbolAddress((void**)&goff,   d_goff);

    float* rbuf  = gi;
    float* zbuf  = gi + (size_t)NN * HD;
    float* inbuf = gi + (size_t)2 * NN * HD;
    float* hnbuf = gh;
    float* h32   = gh + (size_t)NN * HD;

    static bool attr_set = false;
    if (!attr_set) {
        cudaFuncSetAttribute(tf32gemm_abt_kernel,
                             cudaFuncAttributeMaxDynamicSharedMemorySize, GEMM_SMEM_BYTES);
        cudaFuncSetAttribute(gemm_pair_kernel,
                             cudaFuncAttributeMaxDynamicSharedMemorySize, GEMM_SMEM_BYTES);
        cudaFuncSetAttribute(scan_goff_kernel,
                             cudaFuncAttributeMaxDynamicSharedMemorySize, SCAN_SMEM);
        attr_set = true;
    }

    // ---- setup: 4 launches (cnt self-zeroing across replays; zero-init at load) ----
    count_edges_kernel<<<(NE + 255) / 256, 256>>>(dst, cnt);
    scan_goff_kernel<<<1, 1024, SCAN_SMEM>>>(cnt, rowptr, cursor, graph_id, goff);
    place_edges_kernel<<<(NE + 255) / 256, 256>>>(src, dst, etype, cursor, edges);
    embed_weights_kernel<<<(NN * HD + 255) / 256, 256>>>(
        text_idx, emb, h, h32, Wl, wcatT, W_ih, W_hh, wih32, whh32);

    const dim3 g1((NN + 127) / 128, 1);
    const dim3 gp((NN + 127) / 128, 3);

    for (int l = 0; l < NLAYERS; ++l) {
        for (int s = 0; s < NSTEPS; ++s) {
            aggregate_kernel<<<(NN * 32 + 255) / 256, 256>>>(h, rowptr, edges, S, deg);
            tf32gemm_abt_kernel<<<g1, 256, GEMM_SMEM_BYTES>>>(
                S, wcatT + (size_t)l * HD * K3, a,
                NN, K3, HD, deg, bl + l * K3);
            gemm_pair_kernel<<<gp, 256, GEMM_SMEM_BYTES>>>(
                a, h32,
                wih32 + (size_t)l * K3 * HD, whh32 + (size_t)l * K3 * HD,
                b_ih + l * K3, b_hh + l * K3,
                rbuf, zbuf, inbuf, hnbuf);
            gates_kernel<<<(NN * HD + 255) / 256, 256>>>(rbuf, zbuf, inbuf, hnbuf, h, h32);
        }
        mean_kernel<<<NG, HD>>>(h, goff, agg, l + 1);
    }

    mean0_emb_kernel<<<NG, HD>>>(text_idx, emb, goff, agg);
    head_kernel<<<NG, HD>>>(agg, W1, b1, W2, b2, out, out_size);
}

// round 13
// speedup vs baseline: 1.0422x; 1.0351x over previous
#include <cuda_runtime.h>
#include <math.h>
#include <stdint.h>

// ---------------- problem constants ----------------
#define NN 50000         // nodes
#define NE 600000        // edges
#define HD 128           // hidden
#define NG 64            // graphs
#define K3 384           // 3*H
#define NLAYERS 2
#define NSTEPS 2
#define NSTAGE 3

// ---------------- device scratch (no allocs; zero-initialized at load) ----------------
__device__ float d_h[(size_t)NN * HD];
__device__ float d_S[(size_t)NN * K3];
__device__ float d_a[(size_t)NN * HD];
__device__ float d_gi[(size_t)NN * K3];   // planes: r | z | i_n
__device__ float d_gh[(size_t)NN * K3];   // planes: h_n | h32 (rounded h copy)
__device__ float d_deg[(size_t)NN * 3];
__device__ int   d_cnt[NN];               // zeroed by scan kernel after use (replay-safe)
__device__ int   d_rowptr[NN + 1];
__device__ int   d_cursor[NN];
__device__ int   d_edges[NE];
__device__ int   d_goff[NG + 1];
__device__ float d_wcatT[2 * HD * K3];    // per layer: [128 out][384 k], tf32-rounded
__device__ float d_wih32[2 * K3 * HD];    // tf32-rounded W_ih
__device__ float d_whh32[2 * K3 * HD];    // tf32-rounded W_hh
__device__ float d_agg[NG * K3];

__device__ __forceinline__ unsigned cvt_tf32(float x) {
    unsigned r;
    asm("cvt.rna.tf32.f32 %0, %1;" : "=r"(r) : "f"(x));
    return r;
}
__device__ __forceinline__ float rnd_tf32(float x) {
    return __uint_as_float(cvt_tf32(x));
}
__device__ __forceinline__ void f4add(float4& a, const float4& b) {
    a.x += b.x; a.y += b.y; a.z += b.z; a.w += b.w;
}
__device__ __forceinline__ void cp_async16(unsigned saddr, const void* gptr, int szbytes) {
    asm volatile("cp.async.cg.shared.global [%0], [%1], 16, %2;"
                 :: "r"(saddr), "l"(gptr), "r"(szbytes));
}
#define CP_COMMIT() asm volatile("cp.async.commit_group;")
#define CP_WAIT(n)  asm volatile("cp.async.wait_group %0;" :: "n"(n))

// ---------------- setup kernels ----------------

__global__ void count_edges_kernel(const int* __restrict__ dst, int* __restrict__ cnt) {
    int e = blockIdx.x * blockDim.x + threadIdx.x;
    if (e < NE) atomicAdd(&cnt[dst[e]], 1);
}

// coalesced scan: stage counts in smem, chunk-scan, zero cnt for next replay; fuse goff.
#define SCAN_SMEM (NN * 4)
__global__ void scan_goff_kernel(int* __restrict__ cnt, int* __restrict__ rowptr,
                                 int* __restrict__ cursor,
                                 const int* __restrict__ graph_id, int* __restrict__ goff) {
    extern __shared__ int sc[];
    const int CH = (NN + 1023) / 1024;   // 49
    int tid = threadIdx.x;

    for (int q = 0; q < CH; ++q) {
        int i = q * 1024 + tid;
        if (i < NN) { sc[i] = cnt[i]; cnt[i] = 0; }
    }
    __syncthreads();

    int s = tid * CH;
    int e = s + CH < NN ? s + CH : NN;
    int sum = 0;
    for (int i = s; i < e; ++i) sum += sc[i];

    __shared__ int warpsums[32];
    int lane = tid & 31, wid = tid >> 5;
    int v = sum;
#pragma unroll
    for (int off = 1; off < 32; off <<= 1) {
        int t = __shfl_up_sync(0xFFFFFFFFu, v, off);
        if (lane >= off) v += t;
    }
    if (lane == 31) warpsums[wid] = v;
    __syncthreads();
    if (wid == 0) {
        int w = warpsums[lane];
#pragma unroll
        for (int off = 1; off < 32; off <<= 1) {
            int t = __shfl_up_sync(0xFFFFFFFFu, w, off);
            if (lane >= off) w += t;
        }
        warpsums[lane] = w;
    }
    __syncthreads();
    int run = (v - sum) + (wid > 0 ? warpsums[wid - 1] : 0);
    for (int i = s; i < e; ++i) {
        int c = sc[i];
        cursor[i] = run;
        run += c;
        rowptr[i + 1] = run;
    }
    if (tid == 0) rowptr[0] = 0;

    if (tid <= NG) {
        if (tid == NG) goff[NG] = NN;
        else {
            int lo = 0, hi = NN;
            while (lo < hi) {
                int mid = (lo + hi) >> 1;
                if (graph_id[mid] < tid) lo = mid + 1; else hi = mid;
            }
            goff[tid] = lo;
        }
    }
}

__global__ void place_edges_kernel(const int* __restrict__ src, const int* __restrict__ dst,
                                   const int* __restrict__ etype, int* __restrict__ cursor,
                                   int* __restrict__ edges) {
    int e = blockIdx.x * blockDim.x + threadIdx.x;
    if (e >= NE) return;
    int d = dst[e];
    int pos = atomicAdd(&cursor[d], 1);
    edges[pos] = src[e] | (etype[e] << 24);
}

// embed (h + rounded h32) + Wl transpose/round + W_ih/W_hh round — all pure copies
__global__ void embed_weights_kernel(const int* __restrict__ text_idx,
                                     const float* __restrict__ emb,
                                     float* __restrict__ h, float* __restrict__ h32,
                                     const float* __restrict__ Wl, float* __restrict__ wcatT,
                                     const float* __restrict__ Wih, const float* __restrict__ Whh,
                                     float* __restrict__ wih32, float* __restrict__ whh32) {
    int idx = blockIdx.x * blockDim.x + threadIdx.x;
    if (idx < 2 * 3 * 128 * 128) {
        int o  = idx & 127;
        int hh = (idx >> 7) & 127;
        int lt = idx >> 14;
        int t  = lt % 3;
        int l  = lt / 3;
        wcatT[(size_t)l * HD * K3 + (size_t)o * K3 + t * 128 + hh] = rnd_tf32(Wl[idx]);
    }
    if (idx < 2 * K3 * HD) {
        wih32[idx] = rnd_tf32(Wih[idx]);
        whh32[idx] = rnd_tf32(Whh[idx]);
    }
    if (idx < NN * HD) {
        int n = idx >> 7, c = idx & 127;
        float v = emb[(size_t)text_idx[n] * HD + c];
        h[idx] = v;
        h32[idx] = rnd_tf32(v);
    }
}

// segment mean of current h -> agg slot
__global__ void mean_kernel(const float* __restrict__ h, const int* __restrict__ goff,
                            float* __restrict__ agg, int slot) {
    int g = blockIdx.x;
    int c = threadIdx.x; // 128
    int s = goff[g], e = goff[g + 1];
    float a0 = 0.f, a1 = 0.f, a2 = 0.f, a3 = 0.f;
    int r = s;
    for (; r + 4 <= e; r += 4) {
        a0 += h[(size_t)(r + 0) * HD + c];
        a1 += h[(size_t)(r + 1) * HD + c];
        a2 += h[(size_t)(r + 2) * HD + c];
        a3 += h[(size_t)(r + 3) * HD + c];
    }
    for (; r < e; ++r) a0 += h[(size_t)r * HD + c];
    float acc = (a0 + a1) + (a2 + a3);
    float cntf = (float)((e - s) > 0 ? (e - s) : 1);
    agg[g * K3 + slot * HD + c] = acc / cntf;
}

// slot-0 mean recomputed from emb[text_idx] (order-free)
__global__ void mean0_emb_kernel(const int* __restrict__ text_idx,
                                 const float* __restrict__ emb,
                                 const int* __restrict__ goff,
                                 float* __restrict__ agg) {
    int g = blockIdx.x;
    int c = threadIdx.x; // 128
    int s = goff[g], e = goff[g + 1];
    float a0 = 0.f, a1 = 0.f, a2 = 0.f, a3 = 0.f;
    int r = s;
    for (; r + 4 <= e; r += 4) {
        a0 += emb[(size_t)text_idx[r + 0] * HD + c];
        a1 += emb[(size_t)text_idx[r + 1] * HD + c];
        a2 += emb[(size_t)text_idx[r + 2] * HD + c];
        a3 += emb[(size_t)text_idx[r + 3] * HD + c];
    }
    for (; r < e; ++r) a0 += emb[(size_t)text_idx[r] * HD + c];
    float acc = (a0 + a1) + (a2 + a3);
    float cntf = (float)((e - s) > 0 ? (e - s) : 1);
    agg[g * K3 + c] = acc / cntf;
}

// one warp per dst node, 4-way edge unroll for MLP; adds applied in index order
// (bit-identical to sequential loop). S pre-rounded to tf32.
__global__ void aggregate_kernel(const float* __restrict__ h, const int* __restrict__ rowptr,
                                 const int* __restrict__ edges, float* __restrict__ S,
                                 float* __restrict__ deg) {
    int warp = (blockIdx.x * blockDim.x + threadIdx.x) >> 5;
    int lane = threadIdx.x & 31;
    if (warp >= NN) return;
    int s = rowptr[warp], e = rowptr[warp + 1];
    float4 a0 = {0,0,0,0}, a1 = {0,0,0,0}, a2 = {0,0,0,0};
    int c0 = 0, c1 = 0, c2 = 0;
    const float4* h4 = (const float4*)h;

    auto ACC = [&](int p, const float4& v) {
        int t = p >> 24;
        if (t == 0)      { f4add(a0, v); c0++; }
        else if (t == 1) { f4add(a1, v); c1++; }
        else             { f4add(a2, v); c2++; }
    };

    int i = s;
    for (; i + 4 <= e; i += 4) {
        int p0 = edges[i], p1 = edges[i + 1], p2 = edges[i + 2], p3 = edges[i + 3];
        float4 v0 = h4[(size_t)(p0 & 0xFFFFFF) * 32 + lane];
        float4 v1 = h4[(size_t)(p1 & 0xFFFFFF) * 32 + lane];
        float4 v2 = h4[(size_t)(p2 & 0xFFFFFF) * 32 + lane];
        float4 v3 = h4[(size_t)(p3 & 0xFFFFFF) * 32 + lane];
        ACC(p0, v0); ACC(p1, v1); ACC(p2, v2); ACC(p3, v3);
    }
    for (; i < e; ++i) {
        int p = edges[i];
        float4 v = h4[(size_t)(p & 0xFFFFFF) * 32 + lane];
        ACC(p, v);
    }

    uint4* S4 = (uint4*)S;
    size_t base = (size_t)warp * 96;
    S4[base + lane]      = make_uint4(cvt_tf32(a0.x), cvt_tf32(a0.y), cvt_tf32(a0.z), cvt_tf32(a0.w));
    S4[base + 32 + lane] = make_uint4(cvt_tf32(a1.x), cvt_tf32(a1.y), cvt_tf32(a1.z), cvt_tf32(a1.w));
    S4[base + 64 + lane] = make_uint4(cvt_tf32(a2.x), cvt_tf32(a2.y), cvt_tf32(a2.z), cvt_tf32(a2.w));
    if (lane == 0) {
        deg[(size_t)warp * 3 + 0] = (float)c0;
        deg[(size_t)warp * 3 + 1] = (float)c1;
        deg[(size_t)warp * 3 + 2] = (float)c2;
    }
}

// ---------------- TF32 GEMM, cp.async 3-stage pipeline, SINGLE sync per tile ----------
#define TILE_U32   (128 * 36)
#define GEMM_SMEM_BYTES (NSTAGE * TILE_U32 * 2 * 4)

// C[m][j] = sum_k A[m][k]*B[j][k]; +deg-weighted bl3 epilogue; output rounded to tf32
__global__ __launch_bounds__(256, 2) void tf32gemm_abt_kernel(
    const float* __restrict__ A, const float* __restrict__ B, float* __restrict__ C,
    int M, int K, int J,
    const float* __restrict__ deg, const float* __restrict__ bl3)
{
    extern __shared__ unsigned sm[];
    unsigned* As = sm;
    unsigned* Bs = sm + NSTAGE * TILE_U32;

    const int tid = threadIdx.x;
    const int warp = tid >> 5;
    const int lane = tid & 31;
    const int g    = lane >> 2;
    const int tg   = lane & 3;
    const int wm   = (warp >> 2) * 64;
    const int wn   = (warp & 3) * 32;
    const int m0   = blockIdx.x * 128;

    float acc[4][4][4];
#pragma unroll
    for (int mi = 0; mi < 4; ++mi)
#pragma unroll
        for (int ni = 0; ni < 4; ++ni)
#pragma unroll
            for (int q = 0; q < 4; ++q) acc[mi][ni][q] = 0.f;

    const int numT = K >> 5;

    auto GLOAD = [&](int stg, int t) {
        int k0 = t << 5;
        unsigned abase = (unsigned)__cvta_generic_to_shared(As + (size_t)stg * TILE_U32);
        unsigned bbase = (unsigned)__cvta_generic_to_shared(Bs + (size_t)stg * TILE_U32);
#pragma unroll
        for (int u = 0; u < 4; ++u) {
            int f  = tid + u * 256;
            int r  = f >> 3;
            int kq = (f & 7) << 2;
            int gm = m0 + r;
            int gmc = gm < M ? gm : (M - 1);
            cp_async16(abase + (unsigned)(r * 36 + kq) * 4,
                       A + (size_t)gmc * K + k0 + kq, gm < M ? 16 : 0);
            cp_async16(bbase + (unsigned)(r * 36 + kq) * 4,
                       B + (size_t)r * K + k0 + kq, 16);
        }
    };
    auto COMP = [&](int stg) {
        const unsigned* a = As + (size_t)stg * TILE_U32;
        const unsigned* b = Bs + (size_t)stg * TILE_U32;
#pragma unroll
        for (int kk = 0; kk < 32; kk += 8) {
            unsigned af[4][4], bf[4][2];
#pragma unroll
            for (int mi = 0; mi < 4; ++mi) {
                int r = wm + mi * 16 + g;
                af[mi][0] = a[r * 36 + kk + tg];
                af[mi][1] = a[(r + 8) * 36 + kk + tg];
                af[mi][2] = a[r * 36 + kk + tg + 4];
                af[mi][3] = a[(r + 8) * 36 + kk + tg + 4];
            }
#pragma unroll
            for (int ni = 0; ni < 4; ++ni) {
                int c = wn + ni * 8 + g;
                bf[ni][0] = b[c * 36 + kk + tg];
                bf[ni][1] = b[c * 36 + kk + tg + 4];
            }
#pragma unroll
            for (int mi = 0; mi < 4; ++mi)
#pragma unroll
                for (int ni = 0; ni < 4; ++ni) {
                    asm volatile(
                        "mma.sync.aligned.m16n8k8.row.col.f32.tf32.tf32.f32 "
                        "{%0,%1,%2,%3}, {%4,%5,%6,%7}, {%8,%9}, {%0,%1,%2,%3};"
                        : "+f"(acc[mi][ni][0]), "+f"(acc[mi][ni][1]),
                          "+f"(acc[mi][ni][2]), "+f"(acc[mi][ni][3])
                        : "r"(af[mi][0]), "r"(af[mi][1]), "r"(af[mi][2]), "r"(af[mi][3]),
                          "r"(bf[ni][0]), "r"(bf[ni][1]));
                }
        }
    };

    // prologue: tiles 0..NSTAGE-2
#pragma unroll
    for (int s = 0; s < NSTAGE - 1; ++s) {
        GLOAD(s, s);
        CP_COMMIT();
    }
    // single-sync mainloop: wait(t) -> sync -> COMP(t) -> GLOAD(t+NSTAGE-1) -> commit
    for (int t = 0; t < numT; ++t) {
        CP_WAIT(NSTAGE - 2);
        __syncthreads();
        COMP(t % NSTAGE);
        if (t + NSTAGE - 1 < numT) GLOAD((t + NSTAGE - 1) % NSTAGE, t + NSTAGE - 1);
        CP_COMMIT();
    }

#pragma unroll
    for (int mi = 0; mi < 4; ++mi) {
        int r0 = m0 + wm + mi * 16 + g;
        int r1 = r0 + 8;
        float d00 = 0.f, d01 = 0.f, d02 = 0.f, d10 = 0.f, d11 = 0.f, d12 = 0.f;
        if (r0 < M) { d00 = deg[(size_t)r0 * 3]; d01 = deg[(size_t)r0 * 3 + 1]; d02 = deg[(size_t)r0 * 3 + 2]; }
        if (r1 < M) { d10 = deg[(size_t)r1 * 3]; d11 = deg[(size_t)r1 * 3 + 1]; d12 = deg[(size_t)r1 * 3 + 2]; }
#pragma unroll
        for (int ni = 0; ni < 4; ++ni) {
            int cl = wn + ni * 8 + tg * 2;
            float e00 = bl3[cl],       e01 = bl3[cl + 1];
            float e10 = bl3[128 + cl], e11 = bl3[129 + cl];
            float e20 = bl3[256 + cl], e21 = bl3[257 + cl];
            float v00 = acc[mi][ni][0] + d00 * e00 + d01 * e10 + d02 * e20;
            float v01 = acc[mi][ni][1] + d00 * e01 + d01 * e11 + d02 * e21;
            float v10 = acc[mi][ni][2] + d10 * e00 + d11 * e10 + d12 * e20;
            float v11 = acc[mi][ni][3] + d10 * e01 + d11 * e11 + d12 * e21;
            if (r0 < M) *(float2*)(C + (size_t)r0 * J + cl) = make_float2(rnd_tf32(v00), rnd_tf32(v01));
            if (r1 < M) *(float2*)(C + (size_t)r1 * J + cl) = make_float2(rnd_tf32(v10), rnd_tf32(v11));
        }
    }
}

// ---------------- paired GEMM + partial gates; single-sync pipelines ----------------
// grid (391, 3): chunk 0 -> r; chunk 1 -> z; chunk 2 -> i_n and h_n.
__global__ __launch_bounds__(256, 2) void gemm_pair_kernel(
    const float* __restrict__ abuf, const float* __restrict__ hbuf,
    const float* __restrict__ W_ih_l, const float* __restrict__ W_hh_l,
    const float* __restrict__ b_ih_l, const float* __restrict__ b_hh_l,
    float* __restrict__ rbuf, float* __restrict__ zbuf,
    float* __restrict__ inbuf, float* __restrict__ hnbuf)
{
    extern __shared__ unsigned sm[];
    unsigned* As = sm;
    unsigned* Bs = sm + NSTAGE * TILE_U32;

    const int tid  = threadIdx.x;
    const int warp = tid >> 5;
    const int lane = tid & 31;
    const int g    = lane >> 2;
    const int tg   = lane & 3;
    const int wm   = (warp >> 2) * 64;
    const int wn   = (warp & 3) * 32;
    const int m0   = blockIdx.x * 128;
    const int chunk = blockIdx.y;

    float acc[4][4][4];

    auto CLEAR = [&]() {
#pragma unroll
        for (int mi = 0; mi < 4; ++mi)
#pragma unroll
            for (int ni = 0; ni < 4; ++ni)
#pragma unroll
                for (int q = 0; q < 4; ++q) acc[mi][ni][q] = 0.f;
    };
    auto GLOAD = [&](const float* __restrict__ A, const float* __restrict__ B, int stg, int t) {
        int k0 = t << 5;
        unsigned abase = (unsigned)__cvta_generic_to_shared(As + (size_t)stg * TILE_U32);
        unsigned bbase = (unsigned)__cvta_generic_to_shared(Bs + (size_t)stg * TILE_U32);
#pragma unroll
        for (int u = 0; u < 4; ++u) {
            int f  = tid + u * 256;
            int r  = f >> 3;
            int kq = (f & 7) << 2;
            int gm = m0 + r;
            int gmc = gm < NN ? gm : (NN - 1);
            cp_async16(abase + (unsigned)(r * 36 + kq) * 4,
                       A + (size_t)gmc * HD + k0 + kq, gm < NN ? 16 : 0);
            cp_async16(bbase + (unsigned)(r * 36 + kq) * 4,
                       B + (size_t)r * HD + k0 + kq, 16);
        }
    };
    auto COMP = [&](int stg) {
        const unsigned* a = As + (size_t)stg * TILE_U32;
        const unsigned* b = Bs + (size_t)stg * TILE_U32;
#pragma unroll
        for (int kk = 0; kk < 32; kk += 8) {
            unsigned af[4][4], bf[4][2];
#pragma unroll
            for (int mi = 0; mi < 4; ++mi) {
                int r = wm + mi * 16 + g;
                af[mi][0] = a[r * 36 + kk + tg];
                af[mi][1] = a[(r + 8) * 36 + kk + tg];
                af[mi][2] = a[r * 36 + kk + tg + 4];
                af[mi][3] = a[(r + 8) * 36 + kk + tg + 4];
            }
#pragma unroll
            for (int ni = 0; ni < 4; ++ni) {
                int c = wn + ni * 8 + g;
                bf[ni][0] = b[c * 36 + kk + tg];
                bf[ni][1] = b[c * 36 + kk + tg + 4];
            }
#pragma unroll
            for (int mi = 0; mi < 4; ++mi)
#pragma unroll
                for (int ni = 0; ni < 4; ++ni) {
                    asm volatile(
                        "mma.sync.aligned.m16n8k8.row.col.f32.tf32.tf32.f32 "
                        "{%0,%1,%2,%3}, {%4,%5,%6,%7}, {%8,%9}, {%0,%1,%2,%3};"
                        : "+f"(acc[mi][ni][0]), "+f"(acc[mi][ni][1]),
                          "+f"(acc[mi][ni][2]), "+f"(acc[mi][ni][3])
                        : "r"(af[mi][0]), "r"(af[mi][1]), "r"(af[mi][2]), "r"(af[mi][3]),
                          "r"(bf[ni][0]), "r"(bf[ni][1]));
                }
        }
    };
    auto RUN = [&](const float* __restrict__ A, const float* __restrict__ B) {
        const int numT = 4;
#pragma unroll
        for (int s = 0; s < NSTAGE - 1; ++s) {
            GLOAD(A, B, s, s);
            CP_COMMIT();
        }
#pragma unroll
        for (int t = 0; t < numT; ++t) {
            CP_WAIT(NSTAGE - 2);
            __syncthreads();
            COMP(t % NSTAGE);
            if (t + NSTAGE - 1 < numT) GLOAD(A, B, (t + NSTAGE - 1) % NSTAGE, t + NSTAGE - 1);
            CP_COMMIT();
        }
        __syncthreads();   // RUN boundary: protect stages from next RUN's prologue
    };
    auto STORE_EPI = [&](float* __restrict__ out, const float* __restrict__ bias0,
                         const float* __restrict__ bias1, bool sig) {
#pragma unroll
        for (int mi = 0; mi < 4; ++mi) {
            int r0 = m0 + wm + mi * 16 + g;
            int r1 = r0 + 8;
#pragma unroll
            for (int ni = 0; ni < 4; ++ni) {
                int cl = wn + ni * 8 + tg * 2;
                float bb0 = bias0[cl], bb1 = bias0[cl + 1];
                if (bias1) { bb0 += bias1[cl]; bb1 += bias1[cl + 1]; }
                float v00 = acc[mi][ni][0] + bb0, v01 = acc[mi][ni][1] + bb1;
                float v10 = acc[mi][ni][2] + bb0, v11 = acc[mi][ni][3] + bb1;
                if (sig) {
                    v00 = 1.f / (1.f + expf(-v00));
                    v01 = 1.f / (1.f + expf(-v01));
                    v10 = 1.f / (1.f + expf(-v10));
                    v11 = 1.f / (1.f + expf(-v11));
                }
                if (r0 < NN) *(float2*)(out + (size_t)r0 * HD + cl) = make_float2(v00, v01);
                if (r1 < NN) *(float2*)(out + (size_t)r1 * HD + cl) = make_float2(v10, v11);
            }
        }
    };

    if (chunk < 2) {
        CLEAR();
        RUN(abuf, W_ih_l + (size_t)chunk * 128 * HD);
        RUN(hbuf, W_hh_l + (size_t)chunk * 128 * HD);
        STORE_EPI(chunk == 0 ? rbuf : zbuf,
                  b_ih_l + chunk * 128, b_hh_l + chunk * 128, true);
    } else {
        CLEAR();
        RUN(abuf, W_ih_l + (size_t)256 * HD);
        STORE_EPI(inbuf, b_ih_l + 256, nullptr, false);
        CLEAR();
        RUN(hbuf, W_hh_l + (size_t)256 * HD);
        STORE_EPI(hnbuf, b_hh_l + 256, nullptr, false);
    }
}

// ---------------- final gates: h = (1-z)*tanh(i_n + r*h_n) + z*h; also h32 -------------
__global__ void gates_kernel(const float* __restrict__ rbuf, const float* __restrict__ zbuf,
                             const float* __restrict__ inbuf, const float* __restrict__ hnbuf,
                             float* __restrict__ h, float* __restrict__ h32) {
    int idx = blockIdx.x * blockDim.x + threadIdx.x;
    if (idx >= NN * HD) return;
    float r = rbuf[idx], z = zbuf[idx];
    float nc = tanhf(inbuf[idx] + r * hnbuf[idx]);
    float nh = (1.f - z) * nc + z * h[idx];
    h[idx] = nh;
    h32[idx] = rnd_tf32(nh);
}

// ---------------- head ----------------
__global__ void head_kernel(const float* __restrict__ agg, const float* __restrict__ W1,
                            const float* __restrict__ b1, const float* __restrict__ W2,
                            const float* __restrict__ b2, float* __restrict__ out,
                            int out_size) {
    int g = blockIdx.x;
    int o = threadIdx.x; // 128
    __shared__ float sa[K3];
    __shared__ float sx[HD];
    for (int k = o; k < K3; k += HD) sa[k] = agg[g * K3 + k];
    __syncthreads();
    float acc = b1[o];
    for (int k = 0; k < K3; ++k) acc += sa[k] * W1[k * HD + o];
    acc = fmaxf(acc, 0.f);
    sx[o] = acc * W2[o];
    __syncthreads();
    for (int st = 64; st > 0; st >>= 1) {
        if (o < st) sx[o] += sx[o + st];
        __syncthreads();
    }
    if (o == 0 && g < out_size) out[g] = sx[0] + b2[0];
    for (int k = o; k < K3; k += HD) {
        int oi = NG + g * K3 + k;
        if (oi < out_size) out[oi] = sa[k];
    }
}

// ---------------- host launch ----------------
extern "C" void kernel_launch(void* const* d_in, const int* in_sizes, int n_in,
                              void* d_out, int out_size) {
    const int*   text_idx = (const int*)d_in[0];
    const int*   src      = (const int*)d_in[1];
    const int*   dst      = (const int*)d_in[2];
    const int*   etype    = (const int*)d_in[3];
    const int*   graph_id = (const int*)d_in[4];
    const float* emb      = (const float*)d_in[5];
    const float* Wl       = (const float*)d_in[6];
    const float* bl       = (const float*)d_in[7];
    const float* W_ih     = (const float*)d_in[8];
    const float* W_hh     = (const float*)d_in[9];
    const float* b_ih     = (const float*)d_in[10];
    const float* b_hh     = (const float*)d_in[11];
    const float* W1       = (const float*)d_in[12];
    const float* b1       = (const float*)d_in[13];
    const float* W2       = (const float*)d_in[14];
    const float* b2       = (const float*)d_in[15];
    float* out = (float*)d_out;

    float *h, *S, *a, *gi, *gh, *deg, *wcatT, *wih32, *whh32, *agg;
    int *cnt, *rowptr, *cursor, *edges, *goff;
    cudaGetSymbolAddress((void**)&h,      d_h);
    cudaGetSymbolAddress((void**)&S,      d_S);
    cudaGetSymbolAddress((void**)&a,      d_a);
    cudaGetSymbolAddress((void**)&gi,     d_gi);
    cudaGetSymbolAddress((void**)&gh,     d_gh);
    cudaGetSymbolAddress((void**)&deg,    d_deg);
    cudaGetSymbolAddress((void**)&wcatT,  d_wcatT);
    cudaGetSymbolAddress((void**)&wih32,  d_wih32);
    cudaGetSymbolAddress((void**)&whh32,  d_whh32);
    cudaGetSymbolAddress((void**)&agg,    d_agg);
    cudaGetSymbolAddress((void**)&cnt,    d_cnt);
    cudaGetSymbolAddress((void**)&rowptr, d_rowptr);
    cudaGetSymbolAddress((void**)&cursor, d_cursor);
    cudaGetSymbolAddress((void**)&edges,  d_edges);
    cudaGetSymbolAddress((void**)&goff,   d_goff);

    float* rbuf  = gi;
    float* zbuf  = gi + (size_t)NN * HD;
    float* inbuf = gi + (size_t)2 * NN * HD;
    float* hnbuf = gh;
    float* h32   = gh + (size_t)NN * HD;

    static bool attr_set = false;
    if (!attr_set) {
        cudaFuncSetAttribute(tf32gemm_abt_kernel,
                             cudaFuncAttributeMaxDynamicSharedMemorySize, GEMM_SMEM_BYTES);
        cudaFuncSetAttribute(gemm_pair_kernel,
                             cudaFuncAttributeMaxDynamicSharedMemorySize, GEMM_SMEM_BYTES);
        cudaFuncSetAttribute(scan_goff_kernel,
                             cudaFuncAttributeMaxDynamicSharedMemorySize, SCAN_SMEM);
        attr_set = true;
    }

    // ---- setup: 4 launches (cnt self-zeroing across replays; zero-init at load) ----
    count_edges_kernel<<<(NE + 255) / 256, 256>>>(dst, cnt);
    scan_goff_kernel<<<1, 1024, SCAN_SMEM>>>(cnt, rowptr, cursor, graph_id, goff);
    place_edges_kernel<<<(NE + 255) / 256, 256>>>(src, dst, etype, cursor, edges);
    embed_weights_kernel<<<(NN * HD + 255) / 256, 256>>>(
        text_idx, emb, h, h32, Wl, wcatT, W_ih, W_hh, wih32, whh32);

    const dim3 g1((NN + 127) / 128, 1);
    const dim3 gp((NN + 127) / 128, 3);

    for (int l = 0; l < NLAYERS; ++l) {
        for (int s = 0; s < NSTEPS; ++s) {
            aggregate_kernel<<<(NN * 32 + 255) / 256, 256>>>(h, rowptr, edges, S, deg);
            tf32gemm_abt_kernel<<<g1, 256, GEMM_SMEM_BYTES>>>(
                S, wcatT + (size_t)l * HD * K3, a,
                NN, K3, HD, deg, bl + l * K3);
            gemm_pair_kernel<<<gp, 256, GEMM_SMEM_BYTES>>>(
                a, h32,
                wih32 + (size_t)l * K3 * HD, whh32 + (size_t)l * K3 * HD,
                b_ih + l * K3, b_hh + l * K3,
                rbuf, zbuf, inbuf, hnbuf);
            gates_kernel<<<(NN * HD + 255) / 256, 256>>>(rbuf, zbuf, inbuf, hnbuf, h, h32);
        }
        mean_kernel<<<NG, HD>>>(h, goff, agg, l + 1);
    }

    mean0_emb_kernel<<<NG, HD>>>(text_idx, emb, goff, agg);
    head_kernel<<<NG, HD>>>(agg, W1, b1, W2, b2, out, out_size);
}